// round 11
// baseline (speedup 1.0000x reference)
#include <cuda_runtime.h>
#include <math.h>
#include <stdint.h>

// Problem constants (fixed by the dataset)
#define D            128
#define N_NODES_MAX  100000
#define TAU_INV      20.0f                  // 1/0.05
#define INV_2SIG2    (1.0f / 1.125f)        // 1/(2*0.75^2)

#define QSCALE       23.0f                  // int8 quant scale (±127 covers |x|<=5.52)
#define QINV2        (1.0f / (QSCALE * QSCALE))

#define EPW          8                      // edges per warp
#define E_REP_MAX    600000
#define E_ATT_MAX    300000
#define W_REP_MAX    ((E_REP_MAX + EPW - 1) / EPW)
#define W_ATT_MAX    ((E_ATT_MAX + EPW - 1) / EPW)
#define RED_BLOCKS   256
#define RED_THREADS  256
#define NEG_INF      (-__int_as_float(0x7f800000))

// Scratch (no allocation allowed -> device globals)
__device__ int   g_x8[(size_t)N_NODES_MAX * 32];  // packed signed-int8 rows, 128B = 32 words
__device__ int   g_norm[N_NODES_MAX];             // exact integer ||x_i||^2 (quantized)
__device__ float g_warp_m[W_REP_MAX];
__device__ float g_warp_s[W_REP_MAX];
__device__ float g_att_m[W_ATT_MAX];
__device__ float g_part_m[RED_BLOCKS];
__device__ float g_part_s[RED_BLOCKS];
__device__ float g_part_am[RED_BLOCKS];
__device__ float g_m1;
__device__ float g_S2;

__device__ __forceinline__ int q8(float f) {
    int v = __float2int_rn(f * QSCALE);
    return max(-127, min(127, v));
}

// x (f32) -> int8 rows + integer row norms. One warp per node.
__global__ void convert_kernel(const float* __restrict__ x, int n_nodes,
                               int node_base, int node_count) {
    const int node = node_base + blockIdx.x * 8 + (threadIdx.x >> 5);
    const int lane = threadIdx.x & 31;
    if (node >= node_base + node_count || node >= n_nodes) return;
    float4 f = __ldg((const float4*)(x + (size_t)node * D) + lane);
    int v0 = q8(f.x), v1 = q8(f.y), v2 = q8(f.z), v3 = q8(f.w);
    uint32_t p = (uint32_t)(v0 & 255) | ((uint32_t)(v1 & 255) << 8) |
                 ((uint32_t)(v2 & 255) << 16) | ((uint32_t)v3 << 24);
    const int pi = (int)p;
    g_x8[(size_t)node * 32 + lane] = pi;
    // exact integer norm: sum of squares of signed bytes across the row
    int n = __reduce_add_sync(0xffffffffu, __dp4a(pi, pi, 0));
    if (lane == 0) g_norm[node] = n;
}

// Gather: 1 warp = 8 edges. d^2 = norm[i] + norm[j] - 2*dp4a(a,b) (exact int).
// Inner loop: 2 LDG + 1 DP4A + 1 REDUX per edge; norms fetched in epilogue.
__global__ void gather_kernel(const int* __restrict__ att, int E_att,
                              const int* __restrict__ rep, int E_rep,
                              int W_rep, int W_total,
                              float* __restrict__ out) {
    const int w    = blockIdx.x * 8 + (threadIdx.x >> 5);
    const int lane = threadIdx.x & 31;
    if (w >= W_total) return;

    const bool is_rep = (w < W_rep);
    const int* __restrict__ edges = is_rep ? rep : att;
    const int  E  = is_rep ? E_rep : E_att;
    const int  lw = is_rep ? w : (w - W_rep);
    const int  e0 = lw * EPW;

    int s[EPW], d[EPW];
    if (e0 + EPW <= E && (E & 3) == 0) {
        int4 sA = __ldg((const int4*)(edges + e0));
        int4 sB = __ldg((const int4*)(edges + e0 + 4));
        int4 dA = __ldg((const int4*)(edges + E + e0));
        int4 dB = __ldg((const int4*)(edges + E + e0 + 4));
        s[0]=sA.x; s[1]=sA.y; s[2]=sA.z; s[3]=sA.w;
        s[4]=sB.x; s[5]=sB.y; s[6]=sB.z; s[7]=sB.w;
        d[0]=dA.x; d[1]=dA.y; d[2]=dA.z; d[3]=dA.w;
        d[4]=dB.x; d[5]=dB.y; d[6]=dB.z; d[7]=dB.w;
    } else {
        #pragma unroll
        for (int k = 0; k < EPW; k++) {
            int c = min(e0 + k, E - 1);
            s[k] = __ldg(&edges[c]);
            d[k] = __ldg(&edges[E + c]);
        }
    }

    const int* __restrict__ bp = g_x8 + lane;
    int va[EPW], vb[EPW];
    #pragma unroll
    for (int k = 0; k < EPW; k++) va[k] = __ldg(bp + (size_t)s[k] * 32);
    #pragma unroll
    for (int k = 0; k < EPW; k++) vb[k] = __ldg(bp + (size_t)d[k] * 32);

    int dab[EPW];
    #pragma unroll
    for (int k = 0; k < EPW; k++)
        dab[k] = __dp4a(va[k], vb[k], 0);
    #pragma unroll
    for (int k = 0; k < EPW; k++)
        dab[k] = __reduce_add_sync(0xffffffffu, dab[k]);

    // Compact: lane k (k<8) selects edge k's dab via 7-SEL binary tree.
    int t01 = (lane & 1) ? dab[1] : dab[0];
    int t23 = (lane & 1) ? dab[3] : dab[2];
    int t45 = (lane & 1) ? dab[5] : dab[4];
    int t67 = (lane & 1) ? dab[7] : dab[6];
    int t03 = (lane & 2) ? t23 : t01;
    int t47 = (lane & 2) ? t67 : t45;
    int sel = (lane & 4) ? t47 : t03;

    // Lanes 0-7: fetch own edge's node norms (tiny hot array) -> exact d^2.
    const int  c   = min(e0 + lane, E - 1);       // only meaningful for lane<8
    const bool act = (lane < 8) && (e0 + lane < E);
    int si = __ldg(&edges[c]);
    int di = __ldg(&edges[E + c]);
    int d2 = __ldg(&g_norm[si]) + __ldg(&g_norm[di]) - 2 * sel;  // >= 0 exactly

    float d2f = (float)d2 * QINV2;
    float v = __expf(-sqrtf(d2f) * INV_2SIG2) * TAU_INV;   // garbage lanes masked below

    // Warp max over valid edges: v > 0 -> float bits monotone under unsigned cmp.
    unsigned vbits = act ? __float_as_uint(v) : 0u;
    const float m = __uint_as_float(__reduce_max_sync(0xffffffffu, vbits));

    if (is_rep) {
        float e = act ? __expf(v - m) : 0.0f;
        e += __shfl_xor_sync(0xffffffffu, e, 4);   // lanes 0-7 closed under xor {4,2,1}
        e += __shfl_xor_sync(0xffffffffu, e, 2);
        e += __shfl_xor_sync(0xffffffffu, e, 1);
        if (lane == 0) { g_warp_m[lw] = m; g_warp_s[lw] = e; }
    } else {
        if (act) out[e0 + lane] = v;               // coalesced 8-lane store
        if (lane == 0) g_att_m[lw] = m;
    }
}

// Online-softmax merge: (m,s) += (mo,so). Identity = (NEG_INF, 0).
__device__ __forceinline__ void flash_merge(float& m, float& s, float mo, float so) {
    float M = fmaxf(m, mo);
    s = s * __expf(m - M) + so * __expf(mo - M);
    m = M;
}

__global__ void reduce1_kernel(int W_rep, int W_att) {
    __shared__ float sm[RED_THREADS], ss[RED_THREADS], sa[RED_THREADS];
    float m = NEG_INF, s = 0.0f, am = NEG_INF;
    for (int i = blockIdx.x * RED_THREADS + threadIdx.x; i < W_rep;
         i += RED_BLOCKS * RED_THREADS)
        flash_merge(m, s, g_warp_m[i], g_warp_s[i]);
    for (int i = blockIdx.x * RED_THREADS + threadIdx.x; i < W_att;
         i += RED_BLOCKS * RED_THREADS)
        am = fmaxf(am, g_att_m[i]);
    sm[threadIdx.x] = m; ss[threadIdx.x] = s; sa[threadIdx.x] = am;
    __syncthreads();
    #pragma unroll
    for (int sft = RED_THREADS / 2; sft > 0; sft >>= 1) {
        if (threadIdx.x < sft) {
            float mm = sm[threadIdx.x], sss = ss[threadIdx.x];
            flash_merge(mm, sss, sm[threadIdx.x + sft], ss[threadIdx.x + sft]);
            sm[threadIdx.x] = mm; ss[threadIdx.x] = sss;
            sa[threadIdx.x] = fmaxf(sa[threadIdx.x], sa[threadIdx.x + sft]);
        }
        __syncthreads();
    }
    if (threadIdx.x == 0) {
        g_part_m[blockIdx.x]  = sm[0];
        g_part_s[blockIdx.x]  = ss[0];
        g_part_am[blockIdx.x] = sa[0];
    }
}

__global__ void reduce2_kernel() {
    __shared__ float sm[RED_BLOCKS], ss[RED_BLOCKS], sa[RED_BLOCKS];
    sm[threadIdx.x] = g_part_m[threadIdx.x];
    ss[threadIdx.x] = g_part_s[threadIdx.x];
    sa[threadIdx.x] = g_part_am[threadIdx.x];
    __syncthreads();
    #pragma unroll
    for (int sft = RED_BLOCKS / 2; sft > 0; sft >>= 1) {
        if (threadIdx.x < sft) {
            float mm = sm[threadIdx.x], sss = ss[threadIdx.x];
            flash_merge(mm, sss, sm[threadIdx.x + sft], ss[threadIdx.x + sft]);
            sm[threadIdx.x] = mm; ss[threadIdx.x] = sss;
            sa[threadIdx.x] = fmaxf(sa[threadIdx.x], sa[threadIdx.x + sft]);
        }
        __syncthreads();
    }
    if (threadIdx.x == 0) { g_m1 = sa[0]; g_S2 = ss[0]; }
}

__global__ void final_kernel(float* __restrict__ out, int E) {
    const int e = blockIdx.x * blockDim.x + threadIdx.x;
    if (e >= E) return;
    const float num = __expf(out[e] - g_m1);
    out[e] = -__logf(num / (num + g_S2));
}

extern "C" void kernel_launch(void* const* d_in, const int* in_sizes, int n_in,
                              void* d_out, int out_size) {
    const float* x         = (const float*)d_in[0];
    const int*   att_edges = (const int*)d_in[1];
    const int*   rep_edges = (const int*)d_in[2];
    float*       out       = (float*)d_out;

    const int n_elems = in_sizes[0];     // n_nodes * 128
    const int n_nodes = n_elems / D;
    const int E_att   = in_sizes[1] / 2; // [2, E] row-major
    const int E_rep   = in_sizes[2] / 2;

    const int W_rep   = (E_rep + EPW - 1) / EPW;
    const int W_att   = (E_att + EPW - 1) / EPW;
    const int W_total = W_rep + W_att;

    // 1-3) quantize x -> int8 + norms (warp per node), 3-way split keeps ncu on gather
    const int third = (n_nodes + 2) / 3;
    for (int p = 0; p < 3; p++) {
        int nb = p * third;
        int nc = min(third, n_nodes - nb);
        if (nc > 0)
            convert_kernel<<<(nc + 7) / 8, 256>>>(x, n_nodes, nb, nc);
    }

    // 4) gather over both edge sets
    gather_kernel<<<(W_total + 7) / 8, 256>>>(att_edges, E_att, rep_edges, E_rep,
                                              W_rep, W_total, out);

    // 5-6) deterministic flash reduction (rep) + max (att)
    reduce1_kernel<<<RED_BLOCKS, RED_THREADS>>>(W_rep, W_att);
    reduce2_kernel<<<1, RED_BLOCKS>>>();

    // 7) finalize loss in place
    final_kernel<<<(E_att + 255) / 256, 256>>>(out, E_att);
}

// round 12
// speedup vs baseline: 1.0833x; 1.0833x over previous
#include <cuda_runtime.h>
#include <math.h>
#include <stdint.h>

// Problem constants (fixed by the dataset)
#define D            128
#define N_NODES_MAX  100000
#define TAU_INV      20.0f                  // 1/0.05
#define INV_2SIG2    (1.0f / 1.125f)        // 1/(2*0.75^2)

#define QSCALE       23.0f                  // int8 quant scale (±127 covers |x|<=5.52)
#define QINV2        (1.0f / (QSCALE * QSCALE))

#define EPW          8                      // edges per warp
#define E_REP_MAX    600000
#define E_ATT_MAX    300000
#define W_REP_MAX    ((E_REP_MAX + EPW - 1) / EPW)
#define W_ATT_MAX    ((E_ATT_MAX + EPW - 1) / EPW)
#define FIN_BLOCKS   256                    // co-resident on 148 SMs (2/SM max needed)
#define FIN_THREADS  256
#define NEG_INF      (-__int_as_float(0x7f800000))

// Scratch (no allocation allowed -> device globals)
__device__ int   g_x8[(size_t)N_NODES_MAX * 32];  // packed signed-int8 rows, 128B = 32 words
__device__ float g_warp_m[W_REP_MAX];
__device__ float g_warp_s[W_REP_MAX];
__device__ float g_att_m[W_ATT_MAX];
__device__ float g_part_m[FIN_BLOCKS];
__device__ float g_part_s[FIN_BLOCKS];
__device__ float g_part_am[FIN_BLOCKS];
__device__ unsigned g_arrive;

__device__ __forceinline__ int q8(float f) {
    int v = __float2int_rn(f * QSCALE);
    return max(-127, min(127, v));
}

// x (f32) -> int8 rows. One warp per node. Also resets the grid-barrier counter.
__global__ void convert_kernel(const float* __restrict__ x, int n_nodes,
                               int node_base, int node_count) {
    if (node_base == 0 && blockIdx.x == 0 && threadIdx.x == 0) g_arrive = 0;
    const int node = node_base + blockIdx.x * 8 + (threadIdx.x >> 5);
    const int lane = threadIdx.x & 31;
    if (node >= node_base + node_count || node >= n_nodes) return;
    float4 f = __ldg((const float4*)(x + (size_t)node * D) + lane);
    int v0 = q8(f.x), v1 = q8(f.y), v2 = q8(f.z), v3 = q8(f.w);
    uint32_t p = (uint32_t)(v0 & 255) | ((uint32_t)(v1 & 255) << 8) |
                 ((uint32_t)(v2 & 255) << 16) | ((uint32_t)v3 << 24);
    g_x8[(size_t)node * 32 + lane] = (int)p;
}

// Gather (R10 form): 1 warp = 8 edges, int8 rows, 32 lanes per row.
// d^2 = dp4a(a,a)+dp4a(b,b)-2*dp4a(a,b), exact integer, REDUX across warp.
__global__ void gather_kernel(const int* __restrict__ att, int E_att,
                              const int* __restrict__ rep, int E_rep,
                              int W_rep, int W_total,
                              float* __restrict__ out) {
    const int w    = blockIdx.x * 8 + (threadIdx.x >> 5);
    const int lane = threadIdx.x & 31;
    if (w >= W_total) return;

    const bool is_rep = (w < W_rep);
    const int* __restrict__ edges = is_rep ? rep : att;
    const int  E  = is_rep ? E_rep : E_att;
    const int  lw = is_rep ? w : (w - W_rep);
    const int  e0 = lw * EPW;

    int s[EPW], d[EPW];
    if (e0 + EPW <= E && (E & 3) == 0) {
        int4 sA = __ldg((const int4*)(edges + e0));
        int4 sB = __ldg((const int4*)(edges + e0 + 4));
        int4 dA = __ldg((const int4*)(edges + E + e0));
        int4 dB = __ldg((const int4*)(edges + E + e0 + 4));
        s[0]=sA.x; s[1]=sA.y; s[2]=sA.z; s[3]=sA.w;
        s[4]=sB.x; s[5]=sB.y; s[6]=sB.z; s[7]=sB.w;
        d[0]=dA.x; d[1]=dA.y; d[2]=dA.z; d[3]=dA.w;
        d[4]=dB.x; d[5]=dB.y; d[6]=dB.z; d[7]=dB.w;
    } else {
        #pragma unroll
        for (int k = 0; k < EPW; k++) {
            int c = min(e0 + k, E - 1);
            s[k] = __ldg(&edges[c]);
            d[k] = __ldg(&edges[E + c]);
        }
    }

    const int* __restrict__ bp = g_x8 + lane;
    int va[EPW], vb[EPW];
    #pragma unroll
    for (int k = 0; k < EPW; k++) va[k] = __ldg(bp + (size_t)s[k] * 32);
    #pragma unroll
    for (int k = 0; k < EPW; k++) vb[k] = __ldg(bp + (size_t)d[k] * 32);

    int d2[EPW];
    #pragma unroll
    for (int k = 0; k < EPW; k++) {
        int daa = __dp4a(va[k], va[k], 0);
        int dbb = __dp4a(vb[k], vb[k], daa);          // a.a + b.b
        int dab = __dp4a(va[k], vb[k], 0);
        d2[k] = dbb - 2 * dab;                         // >= 0 exactly
    }
    #pragma unroll
    for (int k = 0; k < EPW; k++)
        d2[k] = __reduce_add_sync(0xffffffffu, d2[k]);

    // Compact: lane k (k<8) selects edge k's d2 via 7-SEL binary tree.
    int t01 = (lane & 1) ? d2[1] : d2[0];
    int t23 = (lane & 1) ? d2[3] : d2[2];
    int t45 = (lane & 1) ? d2[5] : d2[4];
    int t67 = (lane & 1) ? d2[7] : d2[6];
    int t03 = (lane & 2) ? t23 : t01;
    int t47 = (lane & 2) ? t67 : t45;
    int sel = (lane & 4) ? t47 : t03;

    const bool act = (lane < 8) && (e0 + lane < E);
    float d2f = (float)sel * QINV2;
    float v = __expf(-sqrtf(d2f) * INV_2SIG2) * TAU_INV;   // garbage lanes masked below

    // Warp max over valid edges: v > 0 -> float bits monotone under unsigned cmp.
    unsigned vbits = act ? __float_as_uint(v) : 0u;
    const float m = __uint_as_float(__reduce_max_sync(0xffffffffu, vbits));

    if (is_rep) {
        float e = act ? __expf(v - m) : 0.0f;
        e += __shfl_xor_sync(0xffffffffu, e, 4);   // lanes 0-7 closed under xor {4,2,1}
        e += __shfl_xor_sync(0xffffffffu, e, 2);
        e += __shfl_xor_sync(0xffffffffu, e, 1);
        if (lane == 0) { g_warp_m[lw] = m; g_warp_s[lw] = e; }
    } else {
        if (act) out[e0 + lane] = v;               // coalesced 8-lane store
        if (lane == 0) g_att_m[lw] = m;
    }
}

// Online-softmax merge: (m,s) += (mo,so). Identity = (NEG_INF, 0).
__device__ __forceinline__ void flash_merge(float& m, float& s, float mo, float so) {
    float M = fmaxf(m, mo);
    s = s * __expf(m - M) + so * __expf(mo - M);
    m = M;
}

// Fused finish: per-block flash partials -> software grid barrier -> every
// block redundantly combines partials (deterministic) -> final transform.
__global__ void finish_kernel(int W_rep, int W_att, float* __restrict__ out, int E_att) {
    __shared__ float sm[FIN_THREADS], ss[FIN_THREADS], sa[FIN_THREADS];
    const int tid = threadIdx.x;

    // Phase A: deterministic per-block partials over fixed slices.
    float m = NEG_INF, s = 0.0f, am = NEG_INF;
    for (int i = blockIdx.x * FIN_THREADS + tid; i < W_rep; i += FIN_BLOCKS * FIN_THREADS)
        flash_merge(m, s, g_warp_m[i], g_warp_s[i]);
    for (int i = blockIdx.x * FIN_THREADS + tid; i < W_att; i += FIN_BLOCKS * FIN_THREADS)
        am = fmaxf(am, g_att_m[i]);
    sm[tid] = m; ss[tid] = s; sa[tid] = am;
    __syncthreads();
    #pragma unroll
    for (int sft = FIN_THREADS / 2; sft > 0; sft >>= 1) {
        if (tid < sft) {
            float mm = sm[tid], sss = ss[tid];
            flash_merge(mm, sss, sm[tid + sft], ss[tid + sft]);
            sm[tid] = mm; ss[tid] = sss;
            sa[tid] = fmaxf(sa[tid], sa[tid + sft]);
        }
        __syncthreads();
    }
    if (tid == 0) {
        g_part_m[blockIdx.x]  = sm[0];
        g_part_s[blockIdx.x]  = ss[0];
        g_part_am[blockIdx.x] = sa[0];
        __threadfence();
        atomicAdd(&g_arrive, 1u);
        // Grid barrier: all FIN_BLOCKS are co-resident (256 blocks, 148 SMs).
        while (atomicAdd(&g_arrive, 0u) < FIN_BLOCKS) { __nanosleep(64); }
    }
    __syncthreads();
    __threadfence();

    // Phase B: every block combines all partials identically (deterministic).
    sm[tid] = g_part_m[tid]; ss[tid] = g_part_s[tid]; sa[tid] = g_part_am[tid];
    __syncthreads();
    #pragma unroll
    for (int sft = FIN_BLOCKS / 2; sft > 0; sft >>= 1) {
        if (tid < sft) {
            float mm = sm[tid], sss = ss[tid];
            flash_merge(mm, sss, sm[tid + sft], ss[tid + sft]);
            sm[tid] = mm; ss[tid] = sss;
            sa[tid] = fmaxf(sa[tid], sa[tid + sft]);
        }
        __syncthreads();
    }
    const float m1 = sa[0];   // attractive max
    const float S2 = ss[0];   // sum exp(sim2 - m2)
    __syncthreads();

    // Phase C: vectorized final transform, grid-strided float4.
    const int E4 = E_att >> 2;
    float4* __restrict__ out4 = reinterpret_cast<float4*>(out);
    for (int i = blockIdx.x * FIN_THREADS + tid; i < E4; i += FIN_BLOCKS * FIN_THREADS) {
        float4 v = out4[i];
        float n0 = __expf(v.x - m1), n1 = __expf(v.y - m1),
              n2 = __expf(v.z - m1), n3 = __expf(v.w - m1);
        v.x = -__logf(n0 / (n0 + S2));
        v.y = -__logf(n1 / (n1 + S2));
        v.z = -__logf(n2 / (n2 + S2));
        v.w = -__logf(n3 / (n3 + S2));
        out4[i] = v;
    }
    for (int e = E4 * 4 + blockIdx.x * FIN_THREADS + tid; e < E_att;
         e += FIN_BLOCKS * FIN_THREADS) {
        float num = __expf(out[e] - m1);
        out[e] = -__logf(num / (num + S2));
    }
}

extern "C" void kernel_launch(void* const* d_in, const int* in_sizes, int n_in,
                              void* d_out, int out_size) {
    const float* x         = (const float*)d_in[0];
    const int*   att_edges = (const int*)d_in[1];
    const int*   rep_edges = (const int*)d_in[2];
    float*       out       = (float*)d_out;

    const int n_elems = in_sizes[0];     // n_nodes * 128
    const int n_nodes = n_elems / D;
    const int E_att   = in_sizes[1] / 2; // [2, E] row-major
    const int E_rep   = in_sizes[2] / 2;

    const int W_rep   = (E_rep + EPW - 1) / EPW;
    const int W_att   = (E_att + EPW - 1) / EPW;
    const int W_total = W_rep + W_att;

    // 1-3) quantize x -> int8 (warp per node), 3-way split keeps ncu on gather
    const int third = (n_nodes + 2) / 3;
    for (int p = 0; p < 3; p++) {
        int nb = p * third;
        int nc = min(third, n_nodes - nb);
        if (nc > 0)
            convert_kernel<<<(nc + 7) / 8, 256>>>(x, n_nodes, nb, nc);
    }

    // 4) gather over both edge sets
    gather_kernel<<<(W_total + 7) / 8, 256>>>(att_edges, E_att, rep_edges, E_rep,
                                              W_rep, W_total, out);

    // 5) fused reduction + final transform (persistent grid + software barrier)
    finish_kernel<<<FIN_BLOCKS, FIN_THREADS>>>(W_rep, W_att, out, E_att);
}

// round 13
// speedup vs baseline: 1.1304x; 1.0435x over previous
#include <cuda_runtime.h>
#include <math.h>
#include <stdint.h>

// Problem constants (fixed by the dataset)
#define D            128
#define N_NODES_MAX  100000
#define TAU_INV      20.0f                  // 1/0.05
#define INV_2SIG2    (1.0f / 1.125f)        // 1/(2*0.75^2)

#define QSCALE       23.0f                  // int8 quant scale (±127 covers |x|<=5.52)
#define QINV2        (1.0f / (QSCALE * QSCALE))

#define EPW          8                      // edges per warp
#define E_REP_MAX    600000
#define E_ATT_MAX    300000
#define W_REP_MAX    ((E_REP_MAX + EPW - 1) / EPW)
#define W_ATT_MAX    ((E_ATT_MAX + EPW - 1) / EPW)
#define FIN_BLOCKS   256                    // co-resident on 148 SMs
#define FIN_THREADS  256
#define NEG_INF      (-__int_as_float(0x7f800000))

// Scratch (no allocation allowed -> device globals)
__device__ int   g_x8[(size_t)N_NODES_MAX * 32];  // packed signed-int8 rows, 128B = 32 words
__device__ float g_warp_m[W_REP_MAX];
__device__ float g_warp_s[W_REP_MAX];
__device__ float g_att_m[W_ATT_MAX];
__device__ float g_part_m[FIN_BLOCKS];
__device__ float g_part_s[FIN_BLOCKS];
__device__ float g_part_am[FIN_BLOCKS];
__device__ unsigned g_arrive;

__device__ __forceinline__ int q8(float f) {
    int v = __float2int_rn(f * QSCALE);
    return max(-127, min(127, v));
}

// x (f32) -> int8 rows. One warp per node, single launch (512-thread blocks).
// Also resets the grid-barrier counter for finish_kernel (graph-replay safe).
__global__ void convert_kernel(const float* __restrict__ x, int n_nodes) {
    if (blockIdx.x == 0 && threadIdx.x == 0) g_arrive = 0;
    const int node = blockIdx.x * 16 + (threadIdx.x >> 5);
    const int lane = threadIdx.x & 31;
    if (node >= n_nodes) return;
    float4 f = __ldg((const float4*)(x + (size_t)node * D) + lane);
    int v0 = q8(f.x), v1 = q8(f.y), v2 = q8(f.z), v3 = q8(f.w);
    uint32_t p = (uint32_t)(v0 & 255) | ((uint32_t)(v1 & 255) << 8) |
                 ((uint32_t)(v2 & 255) << 16) | ((uint32_t)v3 << 24);
    g_x8[(node << 5) | lane] = (int)p;       // 32-bit offset
}

// Gather: 1 warp = 8 edges, int8 rows, 32 lanes per row (LDG.32 each).
// d^2 = dp4a(a,a)+dp4a(b,b)-2*dp4a(a,b), exact integer, REDUX across warp.
// All row addressing in 32-bit offsets (node<<5 | lane).
__global__ void gather_kernel(const int* __restrict__ att, int E_att,
                              const int* __restrict__ rep, int E_rep,
                              int W_rep, int W_total,
                              float* __restrict__ out) {
    const int w    = blockIdx.x * 8 + (threadIdx.x >> 5);
    const int lane = threadIdx.x & 31;
    if (w >= W_total) return;

    const bool is_rep = (w < W_rep);
    const int* __restrict__ edges = is_rep ? rep : att;
    const int  E  = is_rep ? E_rep : E_att;
    const int  lw = is_rep ? w : (w - W_rep);
    const int  e0 = lw * EPW;

    int s[EPW], d[EPW];
    if (e0 + EPW <= E && (E & 3) == 0) {
        int4 sA = __ldg((const int4*)(edges + e0));
        int4 sB = __ldg((const int4*)(edges + e0 + 4));
        int4 dA = __ldg((const int4*)(edges + E + e0));
        int4 dB = __ldg((const int4*)(edges + E + e0 + 4));
        s[0]=sA.x; s[1]=sA.y; s[2]=sA.z; s[3]=sA.w;
        s[4]=sB.x; s[5]=sB.y; s[6]=sB.z; s[7]=sB.w;
        d[0]=dA.x; d[1]=dA.y; d[2]=dA.z; d[3]=dA.w;
        d[4]=dB.x; d[5]=dB.y; d[6]=dB.z; d[7]=dB.w;
    } else {
        #pragma unroll
        for (int k = 0; k < EPW; k++) {
            int c = min(e0 + k, E - 1);
            s[k] = __ldg(&edges[c]);
            d[k] = __ldg(&edges[E + c]);
        }
    }

    int va[EPW], vb[EPW];
    #pragma unroll
    for (int k = 0; k < EPW; k++) va[k] = __ldg(&g_x8[(s[k] << 5) | lane]);
    #pragma unroll
    for (int k = 0; k < EPW; k++) vb[k] = __ldg(&g_x8[(d[k] << 5) | lane]);

    int d2[EPW];
    #pragma unroll
    for (int k = 0; k < EPW; k++) {
        int daa = __dp4a(va[k], va[k], 0);
        int dab = __dp4a(va[k], vb[k], 0);
        int dbb = __dp4a(vb[k], vb[k], daa);          // a.a + b.b
        d2[k] = dbb - 2 * dab;                         // >= 0 exactly
    }
    #pragma unroll
    for (int k = 0; k < EPW; k++)
        d2[k] = __reduce_add_sync(0xffffffffu, d2[k]);

    // Compact: lane k (k<8) selects edge k's d2 via 7-SEL binary tree.
    int t01 = (lane & 1) ? d2[1] : d2[0];
    int t23 = (lane & 1) ? d2[3] : d2[2];
    int t45 = (lane & 1) ? d2[5] : d2[4];
    int t67 = (lane & 1) ? d2[7] : d2[6];
    int t03 = (lane & 2) ? t23 : t01;
    int t47 = (lane & 2) ? t67 : t45;
    int sel = (lane & 4) ? t47 : t03;

    const bool act = (lane < 8) && (e0 + lane < E);
    float d2f = (float)sel * QINV2;
    float v = __expf(-sqrtf(d2f) * INV_2SIG2) * TAU_INV;   // garbage lanes masked below

    // Warp max over valid edges: v > 0 -> float bits monotone under unsigned cmp.
    unsigned vbits = act ? __float_as_uint(v) : 0u;
    const float m = __uint_as_float(__reduce_max_sync(0xffffffffu, vbits));

    if (is_rep) {
        float e = act ? __expf(v - m) : 0.0f;
        e += __shfl_xor_sync(0xffffffffu, e, 4);   // lanes 0-7 closed under xor {4,2,1}
        e += __shfl_xor_sync(0xffffffffu, e, 2);
        e += __shfl_xor_sync(0xffffffffu, e, 1);
        if (lane == 0) { g_warp_m[lw] = m; g_warp_s[lw] = e; }
    } else {
        if (act) out[e0 + lane] = v;               // coalesced 8-lane store
        if (lane == 0) g_att_m[lw] = m;
    }
}

// Online-softmax merge: (m,s) += (mo,so). Identity = (NEG_INF, 0).
__device__ __forceinline__ void flash_merge(float& m, float& s, float mo, float so) {
    float M = fmaxf(m, mo);
    s = s * __expf(m - M) + so * __expf(mo - M);
    m = M;
}

// Fused finish: per-block flash partials -> software grid barrier -> every
// block redundantly combines partials (deterministic) -> final transform.
__global__ void finish_kernel(int W_rep, int W_att, float* __restrict__ out, int E_att) {
    __shared__ float sm[FIN_THREADS], ss[FIN_THREADS], sa[FIN_THREADS];
    const int tid = threadIdx.x;

    // Phase A: deterministic per-block partials over fixed slices.
    float m = NEG_INF, s = 0.0f, am = NEG_INF;
    for (int i = blockIdx.x * FIN_THREADS + tid; i < W_rep; i += FIN_BLOCKS * FIN_THREADS)
        flash_merge(m, s, g_warp_m[i], g_warp_s[i]);
    for (int i = blockIdx.x * FIN_THREADS + tid; i < W_att; i += FIN_BLOCKS * FIN_THREADS)
        am = fmaxf(am, g_att_m[i]);
    sm[tid] = m; ss[tid] = s; sa[tid] = am;
    __syncthreads();
    #pragma unroll
    for (int sft = FIN_THREADS / 2; sft > 0; sft >>= 1) {
        if (tid < sft) {
            float mm = sm[tid], sss = ss[tid];
            flash_merge(mm, sss, sm[tid + sft], ss[tid + sft]);
            sm[tid] = mm; ss[tid] = sss;
            sa[tid] = fmaxf(sa[tid], sa[tid + sft]);
        }
        __syncthreads();
    }
    if (tid == 0) {
        g_part_m[blockIdx.x]  = sm[0];
        g_part_s[blockIdx.x]  = ss[0];
        g_part_am[blockIdx.x] = sa[0];
        __threadfence();
        atomicAdd(&g_arrive, 1u);
        while (atomicAdd(&g_arrive, 0u) < FIN_BLOCKS) { __nanosleep(64); }
    }
    __syncthreads();
    __threadfence();

    // Phase B: every block combines all partials identically (deterministic).
    sm[tid] = g_part_m[tid]; ss[tid] = g_part_s[tid]; sa[tid] = g_part_am[tid];
    __syncthreads();
    #pragma unroll
    for (int sft = FIN_BLOCKS / 2; sft > 0; sft >>= 1) {
        if (tid < sft) {
            float mm = sm[tid], sss = ss[tid];
            flash_merge(mm, sss, sm[tid + sft], ss[tid + sft]);
            sm[tid] = mm; ss[tid] = sss;
            sa[tid] = fmaxf(sa[tid], sa[tid + sft]);
        }
        __syncthreads();
    }
    const float m1 = sa[0];   // attractive max
    const float S2 = ss[0];   // sum exp(sim2 - m2)
    __syncthreads();

    // Phase C: vectorized final transform, grid-strided float4.
    const int E4 = E_att >> 2;
    float4* __restrict__ out4 = reinterpret_cast<float4*>(out);
    for (int i = blockIdx.x * FIN_THREADS + tid; i < E4; i += FIN_BLOCKS * FIN_THREADS) {
        float4 v = out4[i];
        float n0 = __expf(v.x - m1), n1 = __expf(v.y - m1),
              n2 = __expf(v.z - m1), n3 = __expf(v.w - m1);
        v.x = -__logf(n0 / (n0 + S2));
        v.y = -__logf(n1 / (n1 + S2));
        v.z = -__logf(n2 / (n2 + S2));
        v.w = -__logf(n3 / (n3 + S2));
        out4[i] = v;
    }
    for (int e = E4 * 4 + blockIdx.x * FIN_THREADS + tid; e < E_att;
         e += FIN_BLOCKS * FIN_THREADS) {
        float num = __expf(out[e] - m1);
        out[e] = -__logf(num / (num + S2));
    }
}

extern "C" void kernel_launch(void* const* d_in, const int* in_sizes, int n_in,
                              void* d_out, int out_size) {
    const float* x         = (const float*)d_in[0];
    const int*   att_edges = (const int*)d_in[1];
    const int*   rep_edges = (const int*)d_in[2];
    float*       out       = (float*)d_out;

    const int n_elems = in_sizes[0];     // n_nodes * 128
    const int n_nodes = n_elems / D;
    const int E_att   = in_sizes[1] / 2; // [2, E] row-major
    const int E_rep   = in_sizes[2] / 2;

    const int W_rep   = (E_rep + EPW - 1) / EPW;
    const int W_att   = (E_att + EPW - 1) / EPW;
    const int W_total = W_rep + W_att;

    // 1) quantize x -> int8, single launch (16 warps/block)
    convert_kernel<<<(n_nodes + 15) / 16, 512>>>(x, n_nodes);

    // 2) gather over both edge sets
    gather_kernel<<<(W_total + 7) / 8, 256>>>(att_edges, E_att, rep_edges, E_rep,
                                              W_rep, W_total, out);

    // 3) fused reduction + final transform (persistent grid + software barrier)
    finish_kernel<<<FIN_BLOCKS, FIN_THREADS>>>(W_rep, W_att, out, E_att);
}

// round 15
// speedup vs baseline: 1.2363x; 1.0936x over previous
#include <cuda_runtime.h>
#include <math.h>
#include <stdint.h>

// Problem constants (fixed by the dataset)
#define D            128
#define N_NODES_MAX  100000
#define TAU_INV      20.0f                  // 1/0.05
#define INV_2SIG2    (1.0f / 1.125f)        // 1/(2*0.75^2)

#define QSCALE       23.0f                  // int8 quant scale (±127 covers |x|<=5.52)
#define QINV2        (1.0f / (QSCALE * QSCALE))

#define EPW          8                      // edges per warp
#define E_REP_MAX    600000
#define E_ATT_MAX    300000
#define W_REP_MAX    ((E_REP_MAX + EPW - 1) / EPW)
#define W_ATT_MAX    ((E_ATT_MAX + EPW - 1) / EPW)
#define FIN_BLOCKS   256                    // co-resident on 148 SMs
#define FIN_THREADS  256
#define NEG_INF      (-__int_as_float(0x7f800000))

// Scratch (no allocation allowed -> device globals)
__device__ int   g_x8[(size_t)N_NODES_MAX * 32];  // packed signed-int8 rows, 128B = 32 words
__device__ float g_warp_m[W_REP_MAX];
__device__ float g_warp_s[W_REP_MAX];
__device__ float g_att_m[W_ATT_MAX];
__device__ float g_part_m[FIN_BLOCKS];
__device__ float g_part_s[FIN_BLOCKS];
__device__ float g_part_am[FIN_BLOCKS];
__device__ unsigned g_arrive;

__device__ __forceinline__ int q8(float f) {
    int v = __float2int_rn(f * QSCALE);
    return max(-127, min(127, v));
}

// 256-bit load (8 floats) with L2 evict_last residency hint.
__device__ __forceinline__ void ldg_el8(const float* p, float4& a, float4& b) {
    uint32_t r0, r1, r2, r3, r4, r5, r6, r7;
    asm volatile("ld.global.nc.L2::evict_last.v8.b32 {%0,%1,%2,%3,%4,%5,%6,%7}, [%8];"
                 : "=r"(r0), "=r"(r1), "=r"(r2), "=r"(r3),
                   "=r"(r4), "=r"(r5), "=r"(r6), "=r"(r7) : "l"(p));
    a.x = __uint_as_float(r0); a.y = __uint_as_float(r1);
    a.z = __uint_as_float(r2); a.w = __uint_as_float(r3);
    b.x = __uint_as_float(r4); b.y = __uint_as_float(r5);
    b.z = __uint_as_float(r6); b.w = __uint_as_float(r7);
}

__device__ __forceinline__ int quant_word(float4 f) {
    int v0 = q8(f.x), v1 = q8(f.y), v2 = q8(f.z), v3 = q8(f.w);
    uint32_t p = (uint32_t)(v0 & 255) | ((uint32_t)(v1 & 255) << 8) |
                 ((uint32_t)(v2 & 255) << 16) | ((uint32_t)v3 << 24);
    return (int)p;
}

// x -> g_x8 flat map. One thread = two 8-float chunks (MLP=2, 256-bit loads).
// n_oct = n_elems/8 (exact: D=128). Chunk i covers floats [8i, 8i+8) ->
// packed words [2i, 2i+2). Also resets grid-barrier counter (replay-safe).
__global__ void convert_kernel(const float* __restrict__ x, int n_oct) {
    if (blockIdx.x == 0 && threadIdx.x == 0) g_arrive = 0;
    const int half = (n_oct + 1) >> 1;
    const int i = blockIdx.x * blockDim.x + threadIdx.x;
    if (i >= half) return;
    float4 a0, a1, b0, b1;
    ldg_el8(x + (size_t)i * 8, a0, a1);
    const int j = i + half;
    if (j < n_oct) {
        ldg_el8(x + (size_t)j * 8, b0, b1);
        *reinterpret_cast<int2*>(&g_x8[i * 2]) = make_int2(quant_word(a0), quant_word(a1));
        *reinterpret_cast<int2*>(&g_x8[j * 2]) = make_int2(quant_word(b0), quant_word(b1));
    } else {
        *reinterpret_cast<int2*>(&g_x8[i * 2]) = make_int2(quant_word(a0), quant_word(a1));
    }
}

// Gather: 1 warp = 8 edges, int8 rows, 32 lanes per row (LDG.32 each).
// d^2 = dp4a(a,a)+dp4a(b,b)-2*dp4a(a,b), exact integer, REDUX across warp.
// All row addressing in 32-bit offsets (node<<5 | lane).
__global__ void gather_kernel(const int* __restrict__ att, int E_att,
                              const int* __restrict__ rep, int E_rep,
                              int W_rep, int W_total,
                              float* __restrict__ out) {
    const int w    = blockIdx.x * 8 + (threadIdx.x >> 5);
    const int lane = threadIdx.x & 31;
    if (w >= W_total) return;

    const bool is_rep = (w < W_rep);
    const int* __restrict__ edges = is_rep ? rep : att;
    const int  E  = is_rep ? E_rep : E_att;
    const int  lw = is_rep ? w : (w - W_rep);
    const int  e0 = lw * EPW;

    int s[EPW], d[EPW];
    if (e0 + EPW <= E && (E & 3) == 0) {
        int4 sA = __ldg((const int4*)(edges + e0));
        int4 sB = __ldg((const int4*)(edges + e0 + 4));
        int4 dA = __ldg((const int4*)(edges + E + e0));
        int4 dB = __ldg((const int4*)(edges + E + e0 + 4));
        s[0]=sA.x; s[1]=sA.y; s[2]=sA.z; s[3]=sA.w;
        s[4]=sB.x; s[5]=sB.y; s[6]=sB.z; s[7]=sB.w;
        d[0]=dA.x; d[1]=dA.y; d[2]=dA.z; d[3]=dA.w;
        d[4]=dB.x; d[5]=dB.y; d[6]=dB.z; d[7]=dB.w;
    } else {
        #pragma unroll
        for (int k = 0; k < EPW; k++) {
            int c = min(e0 + k, E - 1);
            s[k] = __ldg(&edges[c]);
            d[k] = __ldg(&edges[E + c]);
        }
    }

    int va[EPW], vb[EPW];
    #pragma unroll
    for (int k = 0; k < EPW; k++) va[k] = __ldg(&g_x8[(s[k] << 5) | lane]);
    #pragma unroll
    for (int k = 0; k < EPW; k++) vb[k] = __ldg(&g_x8[(d[k] << 5) | lane]);

    int d2[EPW];
    #pragma unroll
    for (int k = 0; k < EPW; k++) {
        int daa = __dp4a(va[k], va[k], 0);
        int dab = __dp4a(va[k], vb[k], 0);
        int dbb = __dp4a(vb[k], vb[k], daa);          // a.a + b.b
        d2[k] = dbb - 2 * dab;                         // >= 0 exactly
    }
    #pragma unroll
    for (int k = 0; k < EPW; k++)
        d2[k] = __reduce_add_sync(0xffffffffu, d2[k]);

    // Compact: lane k (k<8) selects edge k's d2 via 7-SEL binary tree.
    int t01 = (lane & 1) ? d2[1] : d2[0];
    int t23 = (lane & 1) ? d2[3] : d2[2];
    int t45 = (lane & 1) ? d2[5] : d2[4];
    int t67 = (lane & 1) ? d2[7] : d2[6];
    int t03 = (lane & 2) ? t23 : t01;
    int t47 = (lane & 2) ? t67 : t45;
    int sel = (lane & 4) ? t47 : t03;

    const bool act = (lane < 8) && (e0 + lane < E);
    float d2f = (float)sel * QINV2;
    float v = __expf(-sqrtf(d2f) * INV_2SIG2) * TAU_INV;   // garbage lanes masked below

    // Warp max over valid edges: v > 0 -> float bits monotone under unsigned cmp.
    unsigned vbits = act ? __float_as_uint(v) : 0u;
    const float m = __uint_as_float(__reduce_max_sync(0xffffffffu, vbits));

    if (is_rep) {
        float e = act ? __expf(v - m) : 0.0f;
        e += __shfl_xor_sync(0xffffffffu, e, 4);   // lanes 0-7 closed under xor {4,2,1}
        e += __shfl_xor_sync(0xffffffffu, e, 2);
        e += __shfl_xor_sync(0xffffffffu, e, 1);
        if (lane == 0) { g_warp_m[lw] = m; g_warp_s[lw] = e; }
    } else {
        if (act) out[e0 + lane] = v;               // coalesced 8-lane store
        if (lane == 0) g_att_m[lw] = m;
    }
}

// Online-softmax merge: (m,s) += (mo,so). Identity = (NEG_INF, 0).
__device__ __forceinline__ void flash_merge(float& m, float& s, float mo, float so) {
    float M = fmaxf(m, mo);
    s = s * __expf(m - M) + so * __expf(mo - M);
    m = M;
}

// Fused finish: per-block flash partials -> software grid barrier -> every
// block redundantly combines partials (deterministic) -> final transform.
__global__ void finish_kernel(int W_rep, int W_att, float* __restrict__ out, int E_att) {
    __shared__ float sm[FIN_THREADS], ss[FIN_THREADS], sa[FIN_THREADS];
    const int tid = threadIdx.x;

    // Phase A: deterministic per-block partials over fixed slices.
    float m = NEG_INF, s = 0.0f, am = NEG_INF;
    for (int i = blockIdx.x * FIN_THREADS + tid; i < W_rep; i += FIN_BLOCKS * FIN_THREADS)
        flash_merge(m, s, g_warp_m[i], g_warp_s[i]);
    for (int i = blockIdx.x * FIN_THREADS + tid; i < W_att; i += FIN_BLOCKS * FIN_THREADS)
        am = fmaxf(am, g_att_m[i]);
    sm[tid] = m; ss[tid] = s; sa[tid] = am;
    __syncthreads();
    #pragma unroll
    for (int sft = FIN_THREADS / 2; sft > 0; sft >>= 1) {
        if (tid < sft) {
            float mm = sm[tid], sss = ss[tid];
            flash_merge(mm, sss, sm[tid + sft], ss[tid + sft]);
            sm[tid] = mm; ss[tid] = sss;
            sa[tid] = fmaxf(sa[tid], sa[tid + sft]);
        }
        __syncthreads();
    }
    if (tid == 0) {
        g_part_m[blockIdx.x]  = sm[0];
        g_part_s[blockIdx.x]  = ss[0];
        g_part_am[blockIdx.x] = sa[0];
        __threadfence();
        atomicAdd(&g_arrive, 1u);
        while (atomicAdd(&g_arrive, 0u) < FIN_BLOCKS) { __nanosleep(64); }
    }
    __syncthreads();
    __threadfence();

    // Phase B: every block combines all partials identically (deterministic).
    sm[tid] = g_part_m[tid]; ss[tid] = g_part_s[tid]; sa[tid] = g_part_am[tid];
    __syncthreads();
    #pragma unroll
    for (int sft = FIN_BLOCKS / 2; sft > 0; sft >>= 1) {
        if (tid < sft) {
            float mm = sm[tid], sss = ss[tid];
            flash_merge(mm, sss, sm[tid + sft], ss[tid + sft]);
            sm[tid] = mm; ss[tid] = sss;
            sa[tid] = fmaxf(sa[tid], sa[tid + sft]);
        }
        __syncthreads();
    }
    const float m1 = sa[0];   // attractive max
    const float S2 = ss[0];   // sum exp(sim2 - m2)
    __syncthreads();

    // Phase C: vectorized final transform, grid-strided float4.
    const int E4 = E_att >> 2;
    float4* __restrict__ out4 = reinterpret_cast<float4*>(out);
    for (int i = blockIdx.x * FIN_THREADS + tid; i < E4; i += FIN_BLOCKS * FIN_THREADS) {
        float4 v = out4[i];
        float n0 = __expf(v.x - m1), n1 = __expf(v.y - m1),
              n2 = __expf(v.z - m1), n3 = __expf(v.w - m1);
        v.x = -__logf(n0 / (n0 + S2));
        v.y = -__logf(n1 / (n1 + S2));
        v.z = -__logf(n2 / (n2 + S2));
        v.w = -__logf(n3 / (n3 + S2));
        out4[i] = v;
    }
    for (int e = E4 * 4 + blockIdx.x * FIN_THREADS + tid; e < E_att;
         e += FIN_BLOCKS * FIN_THREADS) {
        float num = __expf(out[e] - m1);
        out[e] = -__logf(num / (num + S2));
    }
}

extern "C" void kernel_launch(void* const* d_in, const int* in_sizes, int n_in,
                              void* d_out, int out_size) {
    const float* x         = (const float*)d_in[0];
    const int*   att_edges = (const int*)d_in[1];
    const int*   rep_edges = (const int*)d_in[2];
    float*       out       = (float*)d_out;

    const int n_elems = in_sizes[0];     // n_nodes * 128
    const int E_att   = in_sizes[1] / 2; // [2, E] row-major
    const int E_rep   = in_sizes[2] / 2;

    const int W_rep   = (E_rep + EPW - 1) / EPW;
    const int W_att   = (E_att + EPW - 1) / EPW;
    const int W_total = W_rep + W_att;

    // 1) quantize x -> int8 (flat map, MLP=2, 256-bit L2-persistent loads)
    const int n_oct = n_elems / 8;       // D=128 -> exact
    const int half  = (n_oct + 1) / 2;
    convert_kernel<<<(half + 255) / 256, 256>>>(x, n_oct);

    // 2) gather over both edge sets
    gather_kernel<<<(W_total + 7) / 8, 256>>>(att_edges, E_att, rep_edges, E_rep,
                                              W_rep, W_total, out);

    // 3) fused reduction + final transform (persistent grid + software barrier)
    finish_kernel<<<FIN_BLOCKS, FIN_THREADS>>>(W_rep, W_att, out, E_att);
}